// round 15
// baseline (speedup 1.0000x reference)
#include <cuda_runtime.h>
#include <cuda_bf16.h>
#include <cstdint>

// EmbeddingLoss: ONE persistent kernel, single grid barrier.
// Phase A: fp32->bf16 swizzled convert + label histogram (on the 7-tile
// blocks). Grid barrier. Phase C: HMMA Gram with CONTIGUOUS tile runs per
// block: A tile reused across a run (3-slot A ring, loaded only when ti
// changes), B in the proven 3-stage cp.async ring, one __syncthreads/tile.
// Diag tiles alias B to A (no B load). Math identical to R10/R14.

namespace {
constexpr int NPIX  = 4096;
constexpr int CH    = 64;
constexpr int BATCH = 4;
constexpr int BM    = 128;
constexpr int TILES = NPIX / BM;                 // 32
constexpr int TRI   = TILES * (TILES + 1) / 2;   // 528
constexpr int NTILES = BATCH * TRI;              // 2112
constexpr int PGRID  = 296;                      // 2 CTAs/SM, all resident
constexpr int MAXT   = 8;                        // blocks 0..39: 8 tiles, rest 7
constexpr int NQ     = BATCH * NPIX * CH / 4;    // 262144 float4 conv units
constexpr int HIST0  = 232;                      // hist on 7-tile blocks
constexpr float MARGIN = 0.5f;
}

__device__ double   g_acc;       // zero-init at load; reset by last block
__device__ unsigned g_done;
__device__ unsigned g_bar;
__device__ int      g_cnt[BATCH * 16];
__device__ __nv_bfloat16 g_ebf[BATCH * NPIX * CH];  // bf16, per-row XOR-swizzled

__device__ __forceinline__ uint32_t smem_u32(const void* p) {
    uint32_t a;
    asm("{ .reg .u64 t; cvta.to.shared.u64 t, %1; cvt.u32.u64 %0, t; }"
        : "=r"(a) : "l"(p));
    return a;
}
__device__ __forceinline__ void ldsm_x4(uint32_t& r0, uint32_t& r1,
                                        uint32_t& r2, uint32_t& r3, uint32_t a) {
    asm volatile("ldmatrix.sync.aligned.m8n8.x4.shared.b16 {%0,%1,%2,%3}, [%4];"
                 : "=r"(r0), "=r"(r1), "=r"(r2), "=r"(r3) : "r"(a));
}
__device__ __forceinline__ void mma16816(float* d, const uint32_t* a,
                                         uint32_t b0, uint32_t b1) {
    asm volatile(
        "mma.sync.aligned.m16n8k16.row.col.f32.bf16.bf16.f32 "
        "{%0,%1,%2,%3}, {%4,%5,%6,%7}, {%8,%9}, {%0,%1,%2,%3};"
        : "+f"(d[0]), "+f"(d[1]), "+f"(d[2]), "+f"(d[3])
        : "r"(a[0]), "r"(a[1]), "r"(a[2]), "r"(a[3]), "r"(b0), "r"(b1));
}
__device__ __forceinline__ uint32_t sw_off(int R, int c) {
    return (uint32_t)(R * 128 + ((c ^ (R & 7)) << 4));
}
__device__ __forceinline__ void cp16(uint32_t s, const void* g) {
    asm volatile("cp.async.cg.shared.global [%0], [%1], 16;" :: "r"(s), "l"(g));
}

__device__ __forceinline__ void grid_barrier(int tid, unsigned target) {
    __syncthreads();
    if (tid == 0) {
        __threadfence();
        atomicAdd(&g_bar, 1u);
        while (*((volatile unsigned*)&g_bar) < target) { }
        __threadfence();
    }
    __syncthreads();
}

__global__ __launch_bounds__(256, 2) void fused_kernel(const float* __restrict__ emb,
                                                       const int* __restrict__ lab,
                                                       float* __restrict__ out) {
    __shared__ __align__(16) __nv_bfloat16 Asm[3][BM * CH];   // A ring, 3 x 16KB
    __shared__ __align__(16) __nv_bfloat16 Bsm[3][BM * CH];   // B ring, 3 x 16KB
    __shared__ int   lrow[3][BM], lcol[3][BM];
    __shared__ float prowf[3][BM], pcol[3][BM];
    __shared__ float swcls[BATCH * 16];
    __shared__ int   tinfo[MAXT];      // b<<12 | ti<<6 | tj
    __shared__ int   taux[MAXT];       // abuf | newA<<2 | diag<<3
    __shared__ float red[8];
    __shared__ int   hist[16];

    const int tid = threadIdx.x;
    const int wid = tid >> 5;
    const int lid = tid & 31;
    const int wr  = wid & 1;
    const int wc  = wid >> 1;
    const int bid = blockIdx.x;

    // ====== Phase A: histogram (7-tile blocks) + convert ====================
    if (bid >= HIST0) {
        if (tid < 16) hist[tid] = 0;
        __syncthreads();
        const int h  = bid - HIST0;
        const int b  = h >> 4;
        const int p0 = (h & 15) * 256;
        atomicAdd(&hist[lab[b * NPIX + p0 + tid] & 15], 1);
        __syncthreads();
        if (tid < 16 && hist[tid] > 0) atomicAdd(&g_cnt[b * 16 + tid], hist[tid]);
    }
    for (int q = bid * 256 + tid; q < NQ; q += PGRID * 256) {
        const int c4 = (q & 15) * 4;
        const int n  = (q >> 4) & (NPIX - 1);
        const float4 v = reinterpret_cast<const float4*>(emb)[q];
        const int chunk = c4 >> 3;
        const int dcol  = ((chunk ^ (n & 7)) << 3) + (c4 & 7);
        __nv_bfloat162 p0(__float2bfloat16(v.x), __float2bfloat16(v.y));
        __nv_bfloat162 p1(__float2bfloat16(v.z), __float2bfloat16(v.w));
        uint2 pk;
        pk.x = *reinterpret_cast<uint32_t*>(&p0);
        pk.y = *reinterpret_cast<uint32_t*>(&p1);
        *reinterpret_cast<uint2*>(g_ebf + ((size_t)(q >> 4)) * CH + dcol) = pk;
    }
    grid_barrier(tid, PGRID);

    if (tid < BATCH * 16) {
        const int c = g_cnt[tid];
        swcls[tid] = (c > 0) ? (1.0f / (float)c) : 0.0f;
    }
    __syncthreads();

    // ====== Phase C: contiguous tile runs, A reuse ==========================
    const uint32_t aS[3] = { smem_u32(Asm[0]), smem_u32(Asm[1]), smem_u32(Asm[2]) };
    const uint32_t bS[3] = { smem_u32(Bsm[0]), smem_u32(Bsm[1]), smem_u32(Bsm[2]) };

    const int nt    = (bid < 40) ? 8 : 7;
    const int start = bid * 7 + (bid < 40 ? bid : 40);

    if (tid == 0) {
        int pb = -1, pti = -1, ab = 0;
        for (int k = 0; k < nt; k++) {
            const int idx = start + k;
            const int b = idx / TRI;
            int t = idx - b * TRI;
            int u = 0;
            while (t >= TILES - u) { t -= TILES - u; u++; }
            const int tj = u + t;
            const bool newA = (b != pb) || (u != pti);
            if (newA && k > 0) ab = (ab == 2) ? 0 : ab + 1;
            tinfo[k] = (b << 12) | (u << 6) | tj;
            taux[k]  = ab | (newA ? 4 : 0) | (u == tj ? 8 : 0);
            pb = b; pti = u;
        }
    }
    __syncthreads();

    auto issue = [&](int k, int bbuf) {
        const int inf = tinfo[k];
        const int aux = taux[k];
        const int b = inf >> 12, ti = (inf >> 6) & 63, tj = inf & 63;
        const int row0 = ti * BM, col0 = tj * BM;
        if (aux & 4) {   // new A row: load A tile into its ring slot
            const char* srcA = (const char*)(g_ebf + ((size_t)(b * NPIX + row0)) * CH);
            const uint32_t dst = aS[aux & 3];
#pragma unroll
            for (int p = 0; p < 4; p++) {
                const int o = (tid + 256 * p) * 16;
                cp16(dst + o, srcA + o);
            }
        }
        if (!(aux & 8)) {  // off-diag: load B tile (diag aliases A)
            const char* srcB = (const char*)(g_ebf + ((size_t)(b * NPIX + col0)) * CH);
            const uint32_t dst = bS[bbuf];
#pragma unroll
            for (int p = 0; p < 4; p++) {
                const int o = (tid + 256 * p) * 16;
                cp16(dst + o, srcB + o);
            }
        }
        if (tid < BM) {
            const int l = lab[b * NPIX + row0 + tid] & 15;
            lrow[bbuf][tid]  = l;
            prowf[bbuf][tid] = ((aux & 8) ? 1.0f : 2.0f) * swcls[(b << 4) + l];
        } else {
            const int u2 = tid - BM;
            const int l = lab[b * NPIX + col0 + u2] & 15;
            lcol[bbuf][u2] = l;
            pcol[bbuf][u2] = swcls[(b << 4) + l];
        }
        asm volatile("cp.async.commit_group;" ::: "memory");
    };

    float tsum = 0.0f;
    issue(0, 0);
    if (nt > 1) issue(1, 1);

    int buf = 0, nbuf = 2;
    for (int k = 0; k < nt; k++) {
        if (k + 1 < nt) asm volatile("cp.async.wait_group 1;" ::: "memory");
        else            asm volatile("cp.async.wait_group 0;" ::: "memory");
        __syncthreads();
        if (k + 2 < nt) issue(k + 2, nbuf);

        const int aux = taux[k];
        const bool diag = (aux & 8) != 0;
        const uint32_t a_base = aS[aux & 3];
        const uint32_t b_base = diag ? a_base : bS[buf];

        float acc[4][4][4];
#pragma unroll
        for (int i = 0; i < 4; i++)
#pragma unroll
            for (int j = 0; j < 4; j++)
#pragma unroll
                for (int e = 0; e < 4; e++) acc[i][j][e] = 0.0f;

        const int aR = 64 * wr + (lid & 15);
        const int bR = 32 * wc + (lid & 15);
        const int hi = lid >> 4;

#pragma unroll
        for (int ks = 0; ks < 4; ks++) {
            const int ck = ks * 2 + hi;
            uint32_t a[4][4];
#pragma unroll
            for (int i = 0; i < 4; i++) {
                const int R = aR + 16 * i;
                ldsm_x4(a[i][0], a[i][1], a[i][2], a[i][3], a_base + sw_off(R, ck));
            }
            uint32_t bb[2][4];
#pragma unroll
            for (int p = 0; p < 2; p++) {
                const int R = bR + 16 * p;
                ldsm_x4(bb[p][0], bb[p][1], bb[p][2], bb[p][3], b_base + sw_off(R, ck));
            }
#pragma unroll
            for (int i = 0; i < 4; i++)
#pragma unroll
                for (int j = 0; j < 4; j++)
                    mma16816(acc[i][j], a[i], bb[j >> 1][j & 1], bb[j >> 1][(j & 1) + 2]);
        }

        const int gr = lid >> 2;
        const int qc = (lid & 3) * 2;
        if (!diag) {
#pragma unroll
            for (int i = 0; i < 4; i++) {
                const int rl0 = 64 * wr + 16 * i + gr, rl1 = rl0 + 8;
                const int  ln0 = lrow[buf][rl0], ln1 = lrow[buf][rl1];
                float rs0 = 0.0f, rs1 = 0.0f;
#pragma unroll
                for (int j = 0; j < 4; j++) {
                    const int cl = 32 * wc + 8 * j + qc;
                    const int  lc0 = lcol[buf][cl],  lc1 = lcol[buf][cl + 1];
                    const float pc0 = pcol[buf][cl], pc1 = pcol[buf][cl + 1];
                    const float s0 = acc[i][j][0], s1 = acc[i][j][1];
                    const float s2 = acc[i][j][2], s3 = acc[i][j][3];
                    const float v0 = (ln0 == lc0) ? (1.0f - s0) : fmaxf(s0 - MARGIN, 0.0f);
                    const float v1 = (ln0 == lc1) ? (1.0f - s1) : fmaxf(s1 - MARGIN, 0.0f);
                    const float v2 = (ln1 == lc0) ? (1.0f - s2) : fmaxf(s2 - MARGIN, 0.0f);
                    const float v3 = (ln1 == lc1) ? (1.0f - s3) : fmaxf(s3 - MARGIN, 0.0f);
                    rs0 = fmaf(v0, pc0, rs0); rs0 = fmaf(v1, pc1, rs0);
                    rs1 = fmaf(v2, pc0, rs1); rs1 = fmaf(v3, pc1, rs1);
                }
                tsum = fmaf(rs0, prowf[buf][rl0], tsum);
                tsum = fmaf(rs1, prowf[buf][rl1], tsum);
            }
        } else {
#pragma unroll
            for (int i = 0; i < 4; i++) {
#pragma unroll
                for (int j = 0; j < 4; j++) {
                    const int cl = 32 * wc + 8 * j + qc;
#pragma unroll
                    for (int e = 0; e < 4; e++) {
                        const int rl = 64 * wr + 16 * i + gr + ((e >> 1) << 3);
                        const int cc = cl + (e & 1);
                        const float s = acc[i][j][e];
                        const float v = (lrow[buf][rl] == lcol[buf][cc])
                                          ? (1.0f - s) : fmaxf(s - MARGIN, 0.0f);
                        float w = 2.0f * prowf[buf][rl] * pcol[buf][cc];
                        if (cc == rl)     w *= 0.5f;
                        else if (cc < rl) w = 0.0f;
                        tsum = fmaf(v, w, tsum);
                    }
                }
            }
        }
        buf  = (buf  == 2) ? 0 : buf + 1;
        nbuf = (nbuf == 2) ? 0 : nbuf + 1;
    }

    // ---- block reduce; last block finalizes and resets state ---------------
#pragma unroll
    for (int o = 16; o > 0; o >>= 1)
        tsum += __shfl_xor_sync(0xffffffffu, tsum, o);
    if (lid == 0) red[wid] = tsum;
    __syncthreads();
    if (tid == 0) {
        float bsum = 0.0f;
#pragma unroll
        for (int wv = 0; wv < 8; wv++) bsum += red[wv];
        atomicAdd(&g_acc, (double)bsum);
        __threadfence();
        const unsigned done = atomicAdd(&g_done, 1u);
        if (done == (unsigned)(PGRID - 1)) {
            __threadfence();
            out[0] = (float)(*((volatile double*)&g_acc) * (double)NPIX);
            g_acc  = 0.0;
            g_done = 0u;
            g_bar  = 0u;
#pragma unroll
            for (int i = 0; i < BATCH * 16; i++) g_cnt[i] = 0;
            __threadfence();
        }
    }
}

extern "C" void kernel_launch(void* const* d_in, const int* in_sizes, int n_in,
                              void* d_out, int out_size) {
    const float* emb = (const float*)d_in[0];
    const int*   lab = (const int*)d_in[1];
    float* out = (float*)d_out;

    fused_kernel<<<PGRID, 256>>>(emb, lab, out);
}

// round 16
// speedup vs baseline: 1.0585x; 1.0585x over previous
#include <cuda_runtime.h>
#include <cuda_bf16.h>
#include <cstdint>

// EmbeddingLoss: ONE persistent kernel, single grid barrier. (R14 + tinfo hoist)
// Phase A: tinfo decode (thread 0, overlapped) + fp32->bf16 swizzled convert
//          (all blocks, grid-stride) + label histogram on blocks 232..295
//          (7-tile blocks; 8-tile critical-path blocks stay prologue-free).
// Grid barrier. Then: per-class smem weight table + R10-proven HMMA Gram
// (3-stage cp.async ring, one __syncthreads/tile, 128x128 upper-tri tiles,
// x2 off-diag), per-block reduce, last-block finalize + state reset.

namespace {
constexpr int NPIX  = 4096;
constexpr int CH    = 64;
constexpr int BATCH = 4;
constexpr int BM    = 128;
constexpr int TILES = NPIX / BM;                 // 32
constexpr int TRI   = TILES * (TILES + 1) / 2;   // 528
constexpr int NTILES = BATCH * TRI;              // 2112
constexpr int PGRID  = 296;                      // 2 CTAs/SM, all resident
constexpr int MAXT   = (NTILES + PGRID - 1) / PGRID;  // 8
constexpr int NQ     = BATCH * NPIX * CH / 4;    // 262144 float4 conv units
constexpr int HIST0  = 232;                      // hist on blocks 232..295
constexpr float MARGIN = 0.5f;
}

__device__ double   g_acc;       // zero-init at load; reset by last block
__device__ unsigned g_done;
__device__ unsigned g_bar;
__device__ int      g_cnt[BATCH * 16];
__device__ __nv_bfloat16 g_ebf[BATCH * NPIX * CH];  // bf16, per-row XOR-swizzled

__device__ __forceinline__ uint32_t smem_u32(const void* p) {
    uint32_t a;
    asm("{ .reg .u64 t; cvta.to.shared.u64 t, %1; cvt.u32.u64 %0, t; }"
        : "=r"(a) : "l"(p));
    return a;
}
__device__ __forceinline__ void ldsm_x4(uint32_t& r0, uint32_t& r1,
                                        uint32_t& r2, uint32_t& r3, uint32_t a) {
    asm volatile("ldmatrix.sync.aligned.m8n8.x4.shared.b16 {%0,%1,%2,%3}, [%4];"
                 : "=r"(r0), "=r"(r1), "=r"(r2), "=r"(r3) : "r"(a));
}
__device__ __forceinline__ void mma16816(float* d, const uint32_t* a,
                                         uint32_t b0, uint32_t b1) {
    asm volatile(
        "mma.sync.aligned.m16n8k16.row.col.f32.bf16.bf16.f32 "
        "{%0,%1,%2,%3}, {%4,%5,%6,%7}, {%8,%9}, {%0,%1,%2,%3};"
        : "+f"(d[0]), "+f"(d[1]), "+f"(d[2]), "+f"(d[3])
        : "r"(a[0]), "r"(a[1]), "r"(a[2]), "r"(a[3]), "r"(b0), "r"(b1));
}
__device__ __forceinline__ uint32_t sw_off(int R, int c) {
    return (uint32_t)(R * 128 + ((c ^ (R & 7)) << 4));
}
__device__ __forceinline__ void cp16(uint32_t s, const void* g) {
    asm volatile("cp.async.cg.shared.global [%0], [%1], 16;" :: "r"(s), "l"(g));
}

// Grid barrier: all PGRID blocks co-resident.
__device__ __forceinline__ void grid_barrier(int tid, unsigned target) {
    __syncthreads();
    if (tid == 0) {
        __threadfence();
        atomicAdd(&g_bar, 1u);
        while (*((volatile unsigned*)&g_bar) < target) { }
        __threadfence();
    }
    __syncthreads();
}

__global__ __launch_bounds__(256, 2) void fused_kernel(const float* __restrict__ emb,
                                                       const int* __restrict__ lab,
                                                       float* __restrict__ out) {
    __shared__ __align__(16) __nv_bfloat16 Asm[3][BM * CH];   // 3 x 16KB
    __shared__ __align__(16) __nv_bfloat16 Bsm[3][BM * CH];   // 3 x 16KB
    __shared__ int   lrow[3][BM], lcol[3][BM];
    __shared__ float prowf[3][BM], pcol[3][BM];
    __shared__ float swcls[BATCH * 16];   // per-class weights 1/cnt
    __shared__ int   tinfo[MAXT];
    __shared__ float red[8];
    __shared__ int   hist[16];

    const int tid = threadIdx.x;
    const int wid = tid >> 5;
    const int lid = tid & 31;
    const int wr  = wid & 1;
    const int wc  = wid >> 1;
    const int bid = blockIdx.x;

    const int nt = (NTILES - bid + PGRID - 1) / PGRID;

    // ====== tile decode first (thread 0) — overlaps conv + barrier wait =====
    if (tid == 0) {
        for (int k = 0; k < nt; k++) {
            const int idx = bid + k * PGRID;
            const int b = idx / TRI;
            int t = idx - b * TRI;
            int u = 0;
            while (t >= TILES - u) { t -= TILES - u; u++; }
            tinfo[k] = (b << 12) | (u << 6) | (u + t);
        }
    }

    // ====== Phase A: histogram (7-tile blocks only) + convert ===============
    if (bid >= HIST0) {
        if (tid < 16) hist[tid] = 0;
        __syncthreads();
        const int h  = bid - HIST0;          // 0..63
        const int b  = h >> 4;               // 16 blocks per batch
        const int p0 = (h & 15) * 256;
        atomicAdd(&hist[lab[b * NPIX + p0 + tid] & 15], 1);
        __syncthreads();
        if (tid < 16 && hist[tid] > 0) atomicAdd(&g_cnt[b * 16 + tid], hist[tid]);
    }
    for (int q = bid * 256 + tid; q < NQ; q += PGRID * 256) {
        const int c4 = (q & 15) * 4;
        const int n  = (q >> 4) & (NPIX - 1);
        const float4 v = reinterpret_cast<const float4*>(emb)[q];
        const int chunk = c4 >> 3;
        const int dcol  = ((chunk ^ (n & 7)) << 3) + (c4 & 7);
        __nv_bfloat162 p0(__float2bfloat16(v.x), __float2bfloat16(v.y));
        __nv_bfloat162 p1(__float2bfloat16(v.z), __float2bfloat16(v.w));
        uint2 pk;
        pk.x = *reinterpret_cast<uint32_t*>(&p0);
        pk.y = *reinterpret_cast<uint32_t*>(&p1);
        *reinterpret_cast<uint2*>(g_ebf + ((size_t)(q >> 4)) * CH + dcol) = pk;
    }
    grid_barrier(tid, PGRID);

    // per-class weight table (bit-identical to 1.0f/(float)cnt)
    if (tid < BATCH * 16) {
        const int c = g_cnt[tid];
        swcls[tid] = (c > 0) ? (1.0f / (float)c) : 0.0f;
    }
    __syncthreads();

    // ====== Phase C: HMMA Gram (R10/R14 verbatim) ===========================
    const uint32_t aS[3] = { smem_u32(Asm[0]), smem_u32(Asm[1]), smem_u32(Asm[2]) };
    const uint32_t bS[3] = { smem_u32(Bsm[0]), smem_u32(Bsm[1]), smem_u32(Bsm[2]) };

    auto issue = [&](int k, int buf) {
        const int inf = tinfo[k];
        const int b = inf >> 12, ti = (inf >> 6) & 63, tj = inf & 63;
        const int row0 = ti * BM, col0 = tj * BM;
        const char* srcA = (const char*)(g_ebf + ((size_t)(b * NPIX + row0)) * CH);
        const char* srcB = (const char*)(g_ebf + ((size_t)(b * NPIX + col0)) * CH);
#pragma unroll
        for (int p = 0; p < 4; p++) {
            const int o = (tid + 256 * p) * 16;
            cp16(aS[buf] + o, srcA + o);
            cp16(bS[buf] + o, srcB + o);
        }
        if (tid < BM) {
            const int l = lab[b * NPIX + row0 + tid] & 15;
            lrow[buf][tid]  = l;
            prowf[buf][tid] = (ti == tj ? 1.0f : 2.0f) * swcls[(b << 4) + l];
        } else {
            const int u = tid - BM;
            const int l = lab[b * NPIX + col0 + u] & 15;
            lcol[buf][u] = l;
            pcol[buf][u] = swcls[(b << 4) + l];
        }
        asm volatile("cp.async.commit_group;" ::: "memory");
    };

    float tsum = 0.0f;
    issue(0, 0);
    if (nt > 1) issue(1, 1);

    int buf = 0, nbuf = 2;
    for (int k = 0; k < nt; k++) {
        if (k + 1 < nt) asm volatile("cp.async.wait_group 1;" ::: "memory");
        else            asm volatile("cp.async.wait_group 0;" ::: "memory");
        __syncthreads();
        if (k + 2 < nt) issue(k + 2, nbuf);

        const int inf = tinfo[k];
        const int ti = (inf >> 6) & 63, tj = inf & 63;
        const bool diag = (ti == tj);

        const uint32_t a_base = aS[buf];
        const uint32_t b_base = bS[buf];

        float acc[4][4][4];
#pragma unroll
        for (int i = 0; i < 4; i++)
#pragma unroll
            for (int j = 0; j < 4; j++)
#pragma unroll
                for (int e = 0; e < 4; e++) acc[i][j][e] = 0.0f;

        const int aR = 64 * wr + (lid & 15);
        const int bR = 32 * wc + (lid & 15);
        const int hi = lid >> 4;

#pragma unroll
        for (int ks = 0; ks < 4; ks++) {
            const int ck = ks * 2 + hi;
            uint32_t a[4][4];
#pragma unroll
            for (int i = 0; i < 4; i++) {
                const int R = aR + 16 * i;
                ldsm_x4(a[i][0], a[i][1], a[i][2], a[i][3], a_base + sw_off(R, ck));
            }
            uint32_t bb[2][4];
#pragma unroll
            for (int p = 0; p < 2; p++) {
                const int R = bR + 16 * p;
                ldsm_x4(bb[p][0], bb[p][1], bb[p][2], bb[p][3], b_base + sw_off(R, ck));
            }
#pragma unroll
            for (int i = 0; i < 4; i++)
#pragma unroll
                for (int j = 0; j < 4; j++)
                    mma16816(acc[i][j], a[i], bb[j >> 1][j & 1], bb[j >> 1][(j & 1) + 2]);
        }

        const int gr = lid >> 2;
        const int qc = (lid & 3) * 2;
        if (!diag) {
#pragma unroll
            for (int i = 0; i < 4; i++) {
                const int rl0 = 64 * wr + 16 * i + gr, rl1 = rl0 + 8;
                const int  ln0 = lrow[buf][rl0], ln1 = lrow[buf][rl1];
                float rs0 = 0.0f, rs1 = 0.0f;
#pragma unroll
                for (int j = 0; j < 4; j++) {
                    const int cl = 32 * wc + 8 * j + qc;
                    const int  lc0 = lcol[buf][cl],  lc1 = lcol[buf][cl + 1];
                    const float pc0 = pcol[buf][cl], pc1 = pcol[buf][cl + 1];
                    const float s0 = acc[i][j][0], s1 = acc[i][j][1];
                    const float s2 = acc[i][j][2], s3 = acc[i][j][3];
                    const float v0 = (ln0 == lc0) ? (1.0f - s0) : fmaxf(s0 - MARGIN, 0.0f);
                    const float v1 = (ln0 == lc1) ? (1.0f - s1) : fmaxf(s1 - MARGIN, 0.0f);
                    const float v2 = (ln1 == lc0) ? (1.0f - s2) : fmaxf(s2 - MARGIN, 0.0f);
                    const float v3 = (ln1 == lc1) ? (1.0f - s3) : fmaxf(s3 - MARGIN, 0.0f);
                    rs0 = fmaf(v0, pc0, rs0); rs0 = fmaf(v1, pc1, rs0);
                    rs1 = fmaf(v2, pc0, rs1); rs1 = fmaf(v3, pc1, rs1);
                }
                tsum = fmaf(rs0, prowf[buf][rl0], tsum);
                tsum = fmaf(rs1, prowf[buf][rl1], tsum);
            }
        } else {
#pragma unroll
            for (int i = 0; i < 4; i++) {
#pragma unroll
                for (int j = 0; j < 4; j++) {
                    const int cl = 32 * wc + 8 * j + qc;
#pragma unroll
                    for (int e = 0; e < 4; e++) {
                        const int rl = 64 * wr + 16 * i + gr + ((e >> 1) << 3);
                        const int cc = cl + (e & 1);
                        const float s = acc[i][j][e];
                        const float v = (lrow[buf][rl] == lcol[buf][cc])
                                          ? (1.0f - s) : fmaxf(s - MARGIN, 0.0f);
                        float w = 2.0f * prowf[buf][rl] * pcol[buf][cc];
                        if (cc == rl)     w *= 0.5f;
                        else if (cc < rl) w = 0.0f;
                        tsum = fmaf(v, w, tsum);
                    }
                }
            }
        }
        buf  = (buf  == 2) ? 0 : buf + 1;
        nbuf = (nbuf == 2) ? 0 : nbuf + 1;
    }

    // ---- block reduce; last block finalizes and resets state ---------------
#pragma unroll
    for (int o = 16; o > 0; o >>= 1)
        tsum += __shfl_xor_sync(0xffffffffu, tsum, o);
    if (lid == 0) red[wid] = tsum;
    __syncthreads();
    if (tid == 0) {
        float bsum = 0.0f;
#pragma unroll
        for (int wv = 0; wv < 8; wv++) bsum += red[wv];
        atomicAdd(&g_acc, (double)bsum);
        __threadfence();
        const unsigned done = atomicAdd(&g_done, 1u);
        if (done == (unsigned)(PGRID - 1)) {
            __threadfence();
            out[0] = (float)(*((volatile double*)&g_acc) * (double)NPIX);
            g_acc  = 0.0;
            g_done = 0u;
            g_bar  = 0u;
#pragma unroll
            for (int i = 0; i < BATCH * 16; i++) g_cnt[i] = 0;
            __threadfence();
        }
    }
}

extern "C" void kernel_launch(void* const* d_in, const int* in_sizes, int n_in,
                              void* d_out, int out_size) {
    const float* emb = (const float*)d_in[0];
    const int*   lab = (const int*)d_in[1];
    float* out = (float*)d_out;

    fused_kernel<<<PGRID, 256>>>(emb, lab, out);
}